// round 1
// baseline (speedup 1.0000x reference)
#include <cuda_runtime.h>

// OSTL one-step forward:
//   I      = x @ W                      (column sums over rows of W)
//   u_new  = sig_tau*u + I
//   s      = (u_new - 1 > 0) ? 1 : 0
//   u_out  = u_new - s                  (V_TH - V_RESET = 1.0)
//   J_new  = sig_tau*J + x[:,None]
//
// Outputs concatenated in d_out: [u_out (8192) | J_new (8192*8192) | s (8192)]

static constexpr int   IN_SZ  = 8192;
static constexpr int   OUT_SZ = 8192;
static constexpr float SIG_TAU = 0.8807970779778823f;  // sigmoid(2.0)

static constexpr int ROWS_PER_BLK = 64;
static constexpr int ROW_BLKS     = IN_SZ / ROWS_PER_BLK;   // 128
static constexpr int COL_BLKS     = OUT_SZ / (256 * 4);     // 8 (256 thr * float4)

// Deterministic matvec partials: one slot per (row-block, column). 4 MiB.
__device__ float g_partial[ROW_BLKS * OUT_SZ];

__global__ void __launch_bounds__(256, 4)
fused_trace_matvec(const float* __restrict__ x,
                   const float* __restrict__ J,
                   const float* __restrict__ W,
                   float*       __restrict__ Jout)
{
    __shared__ float xs[ROWS_PER_BLK];
    const int t    = threadIdx.x;
    const int row0 = blockIdx.y * ROWS_PER_BLK;
    if (t < ROWS_PER_BLK) xs[t] = x[row0 + t];
    __syncthreads();

    const int col4 = blockIdx.x * 256 + t;            // float4 column index (0..2047)
    const float4* __restrict__ J4 = (const float4*)J;
    const float4* __restrict__ W4 = (const float4*)W;
    float4*       __restrict__ O4 = (float4*)Jout;

    float a0 = 0.f, a1 = 0.f, a2 = 0.f, a3 = 0.f;

    #pragma unroll 8
    for (int r = 0; r < ROWS_PER_BLK; ++r) {
        const size_t idx = (size_t)(row0 + r) * (OUT_SZ / 4) + col4;
        const float xi = xs[r];
        const float4 w = W4[idx];
        const float4 j = J4[idx];
        float4 jn;
        jn.x = fmaf(SIG_TAU, j.x, xi);
        jn.y = fmaf(SIG_TAU, j.y, xi);
        jn.z = fmaf(SIG_TAU, j.z, xi);
        jn.w = fmaf(SIG_TAU, j.w, xi);
        O4[idx] = jn;
        a0 = fmaf(xi, w.x, a0);
        a1 = fmaf(xi, w.y, a1);
        a2 = fmaf(xi, w.z, a2);
        a3 = fmaf(xi, w.w, a3);
    }

    float4* P4 = (float4*)(g_partial + (size_t)blockIdx.y * OUT_SZ);
    P4[col4] = make_float4(a0, a1, a2, a3);
}

__global__ void __launch_bounds__(256)
finalize(const float* __restrict__ u,
         float* __restrict__ u_out,
         float* __restrict__ s_out)
{
    const int j = blockIdx.x * blockDim.x + threadIdx.x;
    float sum = SIG_TAU * u[j];
    #pragma unroll 8
    for (int k = 0; k < ROW_BLKS; ++k)
        sum += g_partial[k * OUT_SZ + j];
    const float sp = (sum - 1.0f) > 0.0f ? 1.0f : 0.0f;
    s_out[j] = sp;
    u_out[j] = sum - sp;   // (V_TH - V_RESET) = 1.0
}

extern "C" void kernel_launch(void* const* d_in, const int* in_sizes, int n_in,
                              void* d_out, int out_size)
{
    const float* x = (const float*)d_in[0];
    const float* u = (const float*)d_in[1];
    const float* J = (const float*)d_in[2];
    const float* W = (const float*)d_in[3];

    float* out   = (float*)d_out;
    float* u_out = out;
    float* Jout  = out + OUT_SZ;
    float* s_out = out + OUT_SZ + (size_t)IN_SZ * OUT_SZ;

    fused_trace_matvec<<<dim3(COL_BLKS, ROW_BLKS), 256>>>(x, J, W, Jout);
    finalize<<<OUT_SZ / 256, 256>>>(u, u_out, s_out);
}

// round 2
// speedup vs baseline: 1.0561x; 1.0561x over previous
#include <cuda_runtime.h>

// OSTL one-step forward:
//   I      = x @ W                      (column sums over rows of W)
//   u_new  = sig_tau*u + I
//   s      = (u_new - 1 > 0) ? 1 : 0
//   u_out  = u_new - s                  (V_TH - V_RESET = 1.0)
//   J_new  = sig_tau*J + x[:,None]
//
// Outputs concatenated in d_out: [u_out (8192) | J_new (8192*8192) | s (8192)]

static constexpr int   IN_SZ  = 8192;
static constexpr int   OUT_SZ = 8192;
static constexpr float SIG_TAU = 0.8807970779778823f;  // sigmoid(2.0)

static constexpr int ROWS_PER_BLK = 64;
static constexpr int ROW_BLKS     = IN_SZ / ROWS_PER_BLK;   // 128
static constexpr int COL_BLKS     = OUT_SZ / (256 * 4);     // 8 (256 thr * float4)

// Deterministic matvec partials: one slot per (row-block, column). 4 MiB.
__device__ float g_partial[ROW_BLKS * OUT_SZ];

__global__ void __launch_bounds__(256, 4)
fused_trace_matvec(const float* __restrict__ x,
                   const float* __restrict__ J,
                   const float* __restrict__ W,
                   float*       __restrict__ Jout)
{
    __shared__ float xs[ROWS_PER_BLK];
    const int t    = threadIdx.x;
    const int row0 = blockIdx.y * ROWS_PER_BLK;
    if (t < ROWS_PER_BLK) xs[t] = x[row0 + t];
    __syncthreads();

    const int col4 = blockIdx.x * 256 + t;            // float4 column index (0..2047)
    const float4* __restrict__ J4 = (const float4*)J;
    const float4* __restrict__ W4 = (const float4*)W;
    float4*       __restrict__ O4 = (float4*)Jout;

    float a0 = 0.f, a1 = 0.f, a2 = 0.f, a3 = 0.f;

    #pragma unroll 8
    for (int r = 0; r < ROWS_PER_BLK; ++r) {
        const size_t idx = (size_t)(row0 + r) * (OUT_SZ / 4) + col4;
        const float xi = xs[r];
        const float4 w = W4[idx];
        const float4 j = J4[idx];
        float4 jn;
        jn.x = fmaf(SIG_TAU, j.x, xi);
        jn.y = fmaf(SIG_TAU, j.y, xi);
        jn.z = fmaf(SIG_TAU, j.z, xi);
        jn.w = fmaf(SIG_TAU, j.w, xi);
        O4[idx] = jn;
        a0 = fmaf(xi, w.x, a0);
        a1 = fmaf(xi, w.y, a1);
        a2 = fmaf(xi, w.z, a2);
        a3 = fmaf(xi, w.w, a3);
    }

    float4* P4 = (float4*)(g_partial + (size_t)blockIdx.y * OUT_SZ);
    P4[col4] = make_float4(a0, a1, a2, a3);
}

// Parallel finalize: 256 blocks x 256 threads. Each block owns 32 columns.
// 8 warps split the 128 k-partials (16 each, coalesced across 32 columns),
// then a fixed-order shared-memory tree reduction -> deterministic.
static constexpr int FIN_COLS   = 32;                  // columns per block
static constexpr int FIN_KGRPS  = 8;                   // warps per block
static constexpr int K_PER_GRP  = ROW_BLKS / FIN_KGRPS; // 16

__global__ void __launch_bounds__(256)
finalize(const float* __restrict__ u,
         float* __restrict__ u_out,
         float* __restrict__ s_out)
{
    __shared__ float sdata[FIN_KGRPS][FIN_COLS];

    const int c    = threadIdx.x & 31;        // column within block's group
    const int kg   = threadIdx.x >> 5;        // warp id = k-group
    const int col  = blockIdx.x * FIN_COLS + c;

    float sum = 0.f;
    #pragma unroll
    for (int i = 0; i < K_PER_GRP; ++i) {
        const int k = kg * K_PER_GRP + i;
        sum += g_partial[(size_t)k * OUT_SZ + col];
    }
    sdata[kg][c] = sum;
    __syncthreads();

    if (kg == 0) {
        float tot = SIG_TAU * u[col];
        #pragma unroll
        for (int g = 0; g < FIN_KGRPS; ++g)
            tot += sdata[g][c];
        const float sp = (tot - 1.0f) > 0.0f ? 1.0f : 0.0f;
        s_out[col] = sp;
        u_out[col] = tot - sp;   // (V_TH - V_RESET) = 1.0
    }
}

extern "C" void kernel_launch(void* const* d_in, const int* in_sizes, int n_in,
                              void* d_out, int out_size)
{
    const float* x = (const float*)d_in[0];
    const float* u = (const float*)d_in[1];
    const float* J = (const float*)d_in[2];
    const float* W = (const float*)d_in[3];

    float* out   = (float*)d_out;
    float* u_out = out;
    float* Jout  = out + OUT_SZ;
    float* s_out = out + OUT_SZ + (size_t)IN_SZ * OUT_SZ;

    fused_trace_matvec<<<dim3(COL_BLKS, ROW_BLKS), 256>>>(x, J, W, Jout);
    finalize<<<OUT_SZ / FIN_COLS, 256>>>(u, u_out, s_out);
}